// round 11
// baseline (speedup 1.0000x reference)
#include <cuda_runtime.h>

// ---------------------------------------------------------------------------
// ST_Block: 66-step spatio-temporal orthogonal basis recursion + fused MLP/BN.
//
// R10: GEMM inner loops use packed fma.rn.f32x2 (B300: 3-reg FFMA is
// half-rate, rt_SMSP=2; the packed f32x2 form is the full-rate fp32 path and
// is only reachable via inline PTX). t-columns are processed in pairs: the
// b-operand is read as 64-bit lane pairs from smem, the broadcast a-operand
// is packed once per row via mov.b64 {a,a}. Bit-identical arithmetic.
// Everything else follows R9: persistent kernel, per-chain arrival counters,
// 4-deep g_part, __ldcg/__stcg for mutable slabs.
// ---------------------------------------------------------------------------

#define BB   4
#define CC   16
#define CH   64              // B*C chains
#define NN   512
#define TT   64
#define SLAB (NN*TT)         // 32768 floats per chain slab
#define CSZ  (CH*SLAB)       // floats per full slab
#define NSLAB 7
#define ACCS  6              // slab index reserved for x_st accumulator
#define RTOT  66
#define NB    256            // persistent grid size (co-residency guaranteed)

typedef unsigned long long ull;

__device__ __align__(16) float g_slab[NSLAB * CSZ];   // ~58.7 MB scratch
__device__ float g_part[4][CH][8][6];                 // step-mod-4 dot partials
__device__ float g_theta[BB][RTOT];
__device__ int   g_arrive[CH];                        // per-chain arrival counters

__device__ __forceinline__ float4 ldcg4(const float* p) {
    return __ldcg((const float4*)p);
}
__device__ __forceinline__ void stcg4(float* p, float4 v) {
    __stcg((float4*)p, v);
}

// ---- packed f32x2 helpers (sm_100+) ----
__device__ __forceinline__ void fma2(ull& acc, ull a, ull b) {
    asm("fma.rn.f32x2 %0, %1, %2, %0;" : "+l"(acc) : "l"(a), "l"(b));
}
__device__ __forceinline__ ull pack2(float a) {
    ull r;
    asm("mov.b64 %0, {%1, %1};" : "=l"(r) : "f"(a));
    return r;
}
__device__ __forceinline__ float2 unpack2(ull v) {
    float2 f;
    asm("mov.b64 {%0, %1}, %2;" : "=f"(f.x), "=f"(f.y) : "l"(v));
    return f;
}

__device__ __forceinline__ float warp_sum(float v) {
    v += __shfl_down_sync(0xffffffffu, v, 16);
    v += __shfl_down_sync(0xffffffffu, v, 8);
    v += __shfl_down_sync(0xffffffffu, v, 4);
    v += __shfl_down_sync(0xffffffffu, v, 2);
    v += __shfl_down_sync(0xffffffffu, v, 1);
    return v;
}

// Derive d1, d2, 1/norm, theta from the 6 summed dots (L2-coherent reads).
//   d1 = <V,L>;  d2 = <V,S> - d1*<L,S>
//   ||rst2||^2 = p3 - 2 d1 p1 - 2 d2 p2 + d1^2 p5 + d2^2 p6 + 2 d1 d2 p4
__device__ __forceinline__ void derive_scalars(int buf, int chain, int rUpd,
                                               float* sc) {
    float p0 = 0, p1 = 0, p2 = 0, p3 = 0, p4 = 0, p5 = 0;
    #pragma unroll
    for (int tl = 0; tl < 8; tl++) {
        const float* q = &g_part[buf][chain][tl][0];
        p0 += __ldcg(q + 0); p1 += __ldcg(q + 1); p2 += __ldcg(q + 2);
        p3 += __ldcg(q + 3); p4 += __ldcg(q + 4); p5 += __ldcg(q + 5);
    }
    float d1 = p0;
    float d2 = p1 - d1 * p3;
    float n2 = p2 - 2.f * d1 * p0 - 2.f * d2 * p1
             + d1 * d1 * p4 + d2 * d2 * p5 + 2.f * d1 * d2 * p3;
    sc[0] = d1;
    sc[1] = d2;
    sc[2] = 1.f / fmaxf(sqrtf(fmaxf(n2, 0.f)), 1e-8f);
    sc[3] = g_theta[chain >> 4][rUpd];
}

// Spin until all 8 tiles of `chain` have published step `step` partials,
// then acquire. Called by one thread; caller broadcasts via smem+bar.
__device__ __forceinline__ void wait_chain(int chain, int step) {
    int target = 8 * step;
    while (*(volatile int*)&g_arrive[chain] < target) __nanosleep(32);
    __threadfence();
}

// Tile-local pending update: V <- m = (V - d1 L - d2 S)/norm ; A += theta*m.
// Optionally also deposits m into smem (temporal phases feed the GEMM).
__device__ __forceinline__ void update_tile(int base, int pV, int pL, int pS,
                                            const float* sc, float (*s1)[68],
                                            bool toSmem, int tid) {
    float d1 = sc[0], d2 = sc[1], inv = sc[2], th = sc[3];
    float*       V  = g_slab + pV * CSZ + base;
    const float* Lp = g_slab + pL * CSZ + base;
    const float* Sp = (pS >= 0) ? (g_slab + pS * CSZ + base) : nullptr;
    float*       A  = g_slab + ACCS * CSZ + base;
    #pragma unroll
    for (int it = 0; it < 4; it++) {
        int idx = it * 256 + tid;            // 0..1023 float4s over the tile
        int o = idx * 4;
        float4 v = ldcg4(V + o);
        float4 l = ldcg4(Lp + o);
        float4 s4 = Sp ? ldcg4(Sp + o) : make_float4(0.f, 0.f, 0.f, 0.f);
        float4 m;
        m.x = (v.x - d1 * l.x - d2 * s4.x) * inv;
        m.y = (v.y - d1 * l.y - d2 * s4.y) * inv;
        m.z = (v.z - d1 * l.z - d2 * s4.z) * inv;
        m.w = (v.w - d1 * l.w - d2 * s4.w) * inv;
        stcg4(V + o, m);
        float4 a = *(float4*)(A + o);        // A is tile-owner-private: L1 OK
        a.x += th * m.x; a.y += th * m.y; a.z += th * m.z; a.w += th * m.w;
        *(float4*)(A + o) = a;
        if (toSmem) {
            int n = idx >> 4, t4 = (idx & 15) << 2;
            *(float4*)&s1[n][t4] = m;
        }
    }
}

// ---------------------------------------------------------------------------
// theta: tiny MLP on STE; also resets the per-chain arrival counters
// (device globals persist across graph replays).
// ---------------------------------------------------------------------------
__global__ void k_theta(const float* __restrict__ STE, const float* __restrict__ w1,
                        const float* __restrict__ b1, const float* __restrict__ w2,
                        const float* __restrict__ b2) {
    int idx = threadIdx.x;
    if (idx < CH) g_arrive[idx] = 0;
    if (idx >= BB * RTOT) return;
    int b = idx / RTOT, rr = idx % RTOT;
    int q = rr / 11, p = rr % 11;
    float acc = b2[p];
    #pragma unroll
    for (int s = 0; s < 10; s++) {
        float h1 = b1[q];
        #pragma unroll
        for (int t = 0; t < 5; t++)
            h1 += w1[q * 5 + t] * STE[b * 50 + t * 10 + s];
        acc += w2[p * 10 + s] * h1;
    }
    g_theta[b][rr] = fmaxf(acc, 0.f);
}

// ---------------------------------------------------------------------------
// init: m00 = x / max(||x||_F, eps) into slab 0; acc = theta_0 * m00
// ---------------------------------------------------------------------------
__global__ void __launch_bounds__(256) k_init(const float* __restrict__ x) {
    int chain = blockIdx.x;
    const float* xp = x + chain * SLAB;
    float* m = g_slab + 0 * CSZ + chain * SLAB;
    float* a = g_slab + ACCS * CSZ + chain * SLAB;
    int tid = threadIdx.x;

    float s = 0.f;
    #pragma unroll
    for (int i = 0; i < 32; i++) {
        float4 v = *(const float4*)(xp + (i * 256 + tid) * 4);
        s += v.x * v.x + v.y * v.y + v.z * v.z + v.w * v.w;
    }
    __shared__ float red[8];
    __shared__ float sinv;
    float w = warp_sum(s);
    if ((tid & 31) == 0) red[tid >> 5] = w;
    __syncthreads();
    if (tid == 0) {
        float t = 0.f;
        #pragma unroll
        for (int k = 0; k < 8; k++) t += red[k];
        sinv = 1.f / fmaxf(sqrtf(t), 1e-8f);
    }
    __syncthreads();
    float inv = sinv;
    float th = g_theta[chain >> 4][0];
    #pragma unroll
    for (int i = 0; i < 32; i++) {
        int o = (i * 256 + tid) * 4;
        float4 v = *(const float4*)(xp + o);
        float4 mm, aa;
        mm.x = v.x * inv; mm.y = v.y * inv; mm.z = v.z * inv; mm.w = v.w * inv;
        aa.x = th * mm.x; aa.y = th * mm.y; aa.z = th * mm.z; aa.w = th * mm.w;
        *(float4*)(m + o) = mm;
        *(float4*)(a + o) = aa;
    }
}

// ---------------------------------------------------------------------------
// persistent kernel: all 65 steps + final pending update, per-chain sync.
// Tile tt = (chain = tt>>3, rowTile = tt&7); block b owns tiles {b, b+256}.
// GEMM inner loops use packed f32x2 FMA (full-rate fp32 on B300).
// ---------------------------------------------------------------------------
__global__ void __launch_bounds__(256, 2) k_persist(
    const float* __restrict__ Ls, const float* __restrict__ Lt)
{
    __shared__ float s0[64][68];
    __shared__ float s1[64][68];
    __shared__ float scal[4];
    __shared__ float red[8][6];
    const int tid = threadIdx.x, bid = blockIdx.x;
    const int tx = tid & 15, ty = tid >> 4;

    int last_s = 0, sec_s = -1, last_t = 0, sec_t = -1;
    int pV = -1, pL = -1, pS = -1, pR = 0;
    int r = 1;

    for (int i = 0; i <= 10; i++) {
        if (i > 0) {
            int f = -1;
            #pragma unroll
            for (int k = 5; k >= 0; k--)
                if (k != last_s && k != sec_s && k != last_t && k != sec_t) f = k;
            // ---------------- SPATIAL PHASE (step r) ----------------
            #pragma unroll 1
            for (int tt = bid; tt < 512; tt += NB) {
                int chain = tt >> 3, rt = tt & 7;
                int base = chain * SLAB + rt * 64 * TT;
                if (pV >= 0) {
                    if (tid == 0) {
                        wait_chain(chain, pR);
                        derive_scalars(pR & 3, chain, pR, scal);
                    }
                    __syncthreads();
                    update_tile(base, pV, pL, pS, scal, s1, false, tid);
                }
                const float* Xc = g_slab + last_s * CSZ + chain * SLAB;
                ull accp[4][2] = {};
                for (int kc = 0; kc < 8; kc++) {
                    __syncthreads();
                    #pragma unroll
                    for (int it = 0; it < 4; it++) {
                        int li = it * 256 + tid;
                        int rr = li >> 4, c4 = (li & 15) << 2;
                        *(float4*)&s0[rr][c4] =
                            *(const float4*)(Ls + (rt * 64 + rr) * NN + kc * 64 + c4);
                        *(float4*)&s1[rr][c4] = ldcg4(Xc + (kc * 64 + rr) * TT + c4);
                    }
                    __syncthreads();
                    #pragma unroll 8
                    for (int k = 0; k < 64; k++) {
                        const ull* bp = (const ull*)&s1[k][tx << 2];
                        ull b0 = bp[0], b1 = bp[1];
                        #pragma unroll
                        for (int ii = 0; ii < 4; ii++) {
                            ull a2 = pack2(s0[ty + 16 * ii][k]);
                            fma2(accp[ii][0], a2, b0);
                            fma2(accp[ii][1], a2, b1);
                        }
                    }
                }
                const float* Lr = Xc + rt * 64 * TT;
                const float* S2 = (sec_s >= 0) ? (g_slab + sec_s * CSZ + base) : nullptr;
                float* Vo = g_slab + f * CSZ + base;
                float q1 = 0, q2 = 0, q3 = 0, q4 = 0, q5 = 0, q6 = 0;
                #pragma unroll
                for (int ii = 0; ii < 4; ii++) {
                    int n = ty + 16 * ii;
                    float4 lv = ldcg4(Lr + n * TT + (tx << 2));
                    float4 sv = S2 ? ldcg4(S2 + n * TT + (tx << 2))
                                   : make_float4(0.f, 0.f, 0.f, 0.f);
                    float2 v01 = unpack2(accp[ii][0]);
                    float2 v23 = unpack2(accp[ii][1]);
                    float4 vv = make_float4(v01.x, v01.y, v23.x, v23.y);
                    stcg4(Vo + n * TT + (tx << 2), vv);
                    q1 += vv.x * lv.x + vv.y * lv.y + vv.z * lv.z + vv.w * lv.w;
                    q2 += vv.x * sv.x + vv.y * sv.y + vv.z * sv.z + vv.w * sv.w;
                    q3 += vv.x * vv.x + vv.y * vv.y + vv.z * vv.z + vv.w * vv.w;
                    q4 += lv.x * sv.x + lv.y * sv.y + lv.z * sv.z + lv.w * sv.w;
                    q5 += lv.x * lv.x + lv.y * lv.y + lv.z * lv.z + lv.w * lv.w;
                    q6 += sv.x * sv.x + sv.y * sv.y + sv.z * sv.z + sv.w * sv.w;
                }
                float r6[6] = {q1, q2, q3, q4, q5, q6};
                #pragma unroll
                for (int s = 0; s < 6; s++) {
                    float w = warp_sum(r6[s]);
                    if ((tid & 31) == 0) red[tid >> 5][s] = w;
                }
                __threadfence();            // publish this tile's slab stores
                __syncthreads();
                if (tid == 0) {             // publish partials, then arrive
                    #pragma unroll
                    for (int s = 0; s < 6; s++) {
                        float t = 0.f;
                        #pragma unroll
                        for (int w = 0; w < 8; w++) t += red[w][s];
                        __stcg(&g_part[r & 3][chain][rt][s], t);
                    }
                    __threadfence();
                    atomicAdd(&g_arrive[chain], 1);
                }
                __syncthreads();
            }
            pV = f; pL = last_s; pS = sec_s; pR = r;
            sec_s = last_s; last_s = f; last_t = f; sec_t = -1; r++;
        }
        for (int j = 0; j < 5; j++) {
            int f = -1;
            #pragma unroll
            for (int k = 5; k >= 0; k--)
                if (k != last_s && k != sec_s && k != last_t && k != sec_t) f = k;
            // ---------------- TEMPORAL PHASE (step r) ----------------
            // reload Lt into s0 (spatial phases clobber it)
            #pragma unroll
            for (int it = 0; it < 4; it++) {
                int li = it * 256 + tid;
                int rr = li >> 4, c4 = (li & 15) << 2;
                *(float4*)&s0[rr][c4] = *(const float4*)(Lt + rr * TT + c4);
            }
            #pragma unroll 1
            for (int tt = bid; tt < 512; tt += NB) {
                int chain = tt >> 3, rt = tt & 7;
                int base = chain * SLAB + rt * 64 * TT;
                if (pV >= 0) {              // pV == last_t: prologue feeds GEMM
                    if (tid == 0) {
                        wait_chain(chain, pR);
                        derive_scalars(pR & 3, chain, pR, scal);
                    }
                    __syncthreads();        // scal + s0 ready, s1 free
                    update_tile(base, pV, pL, pS, scal, s1, true, tid);
                } else {
                    __syncthreads();        // s0 ready, s1 free
                    const float* X = g_slab + last_t * CSZ + base;
                    #pragma unroll
                    for (int it = 0; it < 4; it++) {
                        int idx = it * 256 + tid;
                        int n = idx >> 4, t4 = (idx & 15) << 2;
                        *(float4*)&s1[n][t4] = ldcg4(X + n * TT + t4);
                    }
                }
                __syncthreads();            // s1 ready
                ull accp[4][2] = {};
                #pragma unroll 8
                for (int k = 0; k < 64; k++) {
                    const ull* bp = (const ull*)&s0[k][tx << 2];   // Lt[k][u]
                    ull b0 = bp[0], b1 = bp[1];
                    #pragma unroll
                    for (int ii = 0; ii < 4; ii++) {
                        ull a2 = pack2(s1[ty + 16 * ii][k]);
                        fma2(accp[ii][0], a2, b0);
                        fma2(accp[ii][1], a2, b1);
                    }
                }
                const float* S2 = (sec_t >= 0) ? (g_slab + sec_t * CSZ + base) : nullptr;
                float* Vo = g_slab + f * CSZ + base;
                float q1 = 0, q2 = 0, q3 = 0, q4 = 0, q5 = 0, q6 = 0;
                #pragma unroll
                for (int ii = 0; ii < 4; ii++) {
                    int n = ty + 16 * ii;
                    float4 lv = *(float4*)&s1[n][tx << 2];      // m_last at (n,u)
                    float4 sv = S2 ? ldcg4(S2 + n * TT + (tx << 2))
                                   : make_float4(0.f, 0.f, 0.f, 0.f);
                    float2 v01 = unpack2(accp[ii][0]);
                    float2 v23 = unpack2(accp[ii][1]);
                    float4 vv = make_float4(v01.x, v01.y, v23.x, v23.y);
                    stcg4(Vo + n * TT + (tx << 2), vv);
                    q1 += vv.x * lv.x + vv.y * lv.y + vv.z * lv.z + vv.w * lv.w;
                    q2 += vv.x * sv.x + vv.y * sv.y + vv.z * sv.z + vv.w * sv.w;
                    q3 += vv.x * vv.x + vv.y * vv.y + vv.z * vv.z + vv.w * vv.w;
                    q4 += lv.x * sv.x + lv.y * sv.y + lv.z * sv.z + lv.w * sv.w;
                    q5 += lv.x * lv.x + lv.y * lv.y + lv.z * lv.z + lv.w * lv.w;
                    q6 += sv.x * sv.x + sv.y * sv.y + sv.z * sv.z + sv.w * sv.w;
                }
                float r6[6] = {q1, q2, q3, q4, q5, q6};
                #pragma unroll
                for (int s = 0; s < 6; s++) {
                    float w = warp_sum(r6[s]);
                    if ((tid & 31) == 0) red[tid >> 5][s] = w;
                }
                __threadfence();            // publish this tile's slab stores
                __syncthreads();
                if (tid == 0) {
                    #pragma unroll
                    for (int s = 0; s < 6; s++) {
                        float t = 0.f;
                        #pragma unroll
                        for (int w = 0; w < 8; w++) t += red[w][s];
                        __stcg(&g_part[r & 3][chain][rt][s], t);
                    }
                    __threadfence();
                    atomicAdd(&g_arrive[chain], 1);
                }
                __syncthreads();
            }
            pV = f; pL = last_t; pS = sec_t; pR = r;
            sec_t = last_t; last_t = f; r++;
        }
    }
    // ---------------- final pending update (r = 65): A += theta*m ----------
    #pragma unroll 1
    for (int tt = bid; tt < 512; tt += NB) {
        int chain = tt >> 3, rt = tt & 7;
        int base = chain * SLAB + rt * 64 * TT;
        if (tid == 0) {
            wait_chain(chain, pR);
            derive_scalars(pR & 3, chain, pR, scal);
        }
        __syncthreads();
        float d1 = scal[0], d2 = scal[1], inv = scal[2], th = scal[3];
        const float* V  = g_slab + pV * CSZ + base;
        const float* Lp = g_slab + pL * CSZ + base;
        const float* Sp = (pS >= 0) ? (g_slab + pS * CSZ + base) : nullptr;
        float* A = g_slab + ACCS * CSZ + base;
        #pragma unroll
        for (int it = 0; it < 4; it++) {
            int o = (it * 256 + tid) * 4;
            float4 v = ldcg4(V + o);
            float4 l = ldcg4(Lp + o);
            float4 s4 = Sp ? ldcg4(Sp + o) : make_float4(0.f, 0.f, 0.f, 0.f);
            float4 a = *(float4*)(A + o);
            a.x += th * (v.x - d1 * l.x - d2 * s4.x) * inv;
            a.y += th * (v.y - d1 * l.y - d2 * s4.y) * inv;
            a.z += th * (v.z - d1 * l.z - d2 * s4.z) * inv;
            a.w += th * (v.w - d1 * l.w - d2 * s4.w) * inv;
            *(float4*)(A + o) = a;
        }
        __syncthreads();
    }
}

// ---------------------------------------------------------------------------
// final: out[b,o,n,t] = BN(W_mlp @ cat(x, x_st) + b)   with BN folded into W,b
// R10: __launch_bounds__(256,3) caps regs (<=85) -> 3 CTAs/SM, occ 37.5%.
// ---------------------------------------------------------------------------
__global__ void __launch_bounds__(256, 3) k_final(const float* __restrict__ x,
                                                  const float* __restrict__ wm,
                                                  const float* __restrict__ bm,
                                                  const float* __restrict__ gam,
                                                  const float* __restrict__ bet,
                                                  const float* __restrict__ mea,
                                                  const float* __restrict__ var,
                                                  float* __restrict__ out) {
    int b = blockIdx.x;
    int ng = blockIdx.y;                 // group of 4 n values
    __shared__ float sV[4][32][65];
    __shared__ float sW[64][32];
    __shared__ float sb2[64];
    int tid = threadIdx.x;

    for (int i = tid; i < 2048; i += 256) {
        int o = i >> 5, c = i & 31;
        float inv = gam[o] * rsqrtf(var[o] + 1e-5f);
        sW[o][c] = wm[o * 32 + c] * inv;
    }
    if (tid < 64) {
        float inv = gam[tid] * rsqrtf(var[tid] + 1e-5f);
        sb2[tid] = bm[tid] * inv + bet[tid] - mea[tid] * inv;
    }
    for (int i = tid; i < 8192; i += 256) {
        int t = i & 63, c = (i >> 6) & 31, nn = i >> 11;
        int n = ng * 4 + nn;
        float val;
        if (c < 16) val = x[((b * CC + c) * NN + n) * TT + t];
        else        val = g_slab[ACCS * CSZ + (b * CC + (c - 16)) * SLAB + n * TT + t];
        sV[nn][c][t] = val;
    }
    __syncthreads();

    int tg = tid & 63, og = tid >> 6;
    #pragma unroll 1
    for (int oo = 0; oo < 16; oo++) {
        int o = og * 16 + oo;
        float bb = sb2[o];
        float a0 = bb, a1 = bb, a2 = bb, a3 = bb;
        #pragma unroll
        for (int c = 0; c < 32; c++) {
            float w = sW[o][c];
            a0 += w * sV[0][c][tg];
            a1 += w * sV[1][c][tg];
            a2 += w * sV[2][c][tg];
            a3 += w * sV[3][c][tg];
        }
        int n0 = ng * 4;
        float* op = out + ((b * 64 + o) * NN + n0) * TT + tg;
        op[0 * TT] = a0;
        op[1 * TT] = a1;
        op[2 * TT] = a2;
        op[3 * TT] = a3;
    }
}

// ---------------------------------------------------------------------------
// host: 4-node launch sequence (graph-capturable: launches only)
// ---------------------------------------------------------------------------
extern "C" void kernel_launch(void* const* d_in, const int* in_sizes, int n_in,
                              void* d_out, int out_size) {
    const float* x   = (const float*)d_in[0];
    const float* Ls  = (const float*)d_in[1];
    const float* Lt  = (const float*)d_in[2];
    const float* STE = (const float*)d_in[3];
    const float* w1  = (const float*)d_in[4];
    const float* b1  = (const float*)d_in[5];
    const float* w2  = (const float*)d_in[6];
    const float* b2  = (const float*)d_in[7];
    const float* wm  = (const float*)d_in[8];
    const float* bm  = (const float*)d_in[9];
    const float* gam = (const float*)d_in[10];
    const float* bet = (const float*)d_in[11];
    const float* mea = (const float*)d_in[12];
    const float* var = (const float*)d_in[13];
    float* out = (float*)d_out;
    (void)in_sizes; (void)n_in; (void)out_size;

    k_theta<<<1, 288>>>(STE, w1, b1, w2, b2);
    k_init<<<64, 256>>>(x);
    k_persist<<<NB, 256>>>(Ls, Lt);
    k_final<<<dim3(4, 128), 256>>>(x, wm, bm, gam, bet, mea, var, out);
}

// round 12
// speedup vs baseline: 1.0097x; 1.0097x over previous
#include <cuda_runtime.h>

// ---------------------------------------------------------------------------
// ST_Block: 66-step spatio-temporal orthogonal basis recursion + fused MLP/BN.
//
// R11: temporal recursion is row-tile-local, so its state never touches gmem:
//  - raw GEMM output V stays in REGISTERS across the phase boundary,
//  - the last two normalized bases m_{k-1}, m_{k-2} live in two ping-pong
//    smem buffers per tile (m_k -> B[k&1]),
//  - normalization (needs chain-global scalars from g_part) happens
//    regs->smem; only m_{i,0} is written to gmem (next spatial GEMM input).
// gmem slabs: 3 rotating spatial-m slabs + x_st accumulator (32 MB total).
// Per-chain arrival counters (R9) unchanged; 4-deep g_part; 256 co-resident
// CTAs (104.4 KB dyn smem -> 2/SM, regs <=128 via launch bounds).
// ---------------------------------------------------------------------------

#define BB   4
#define CC   16
#define CH   64              // B*C chains
#define NN   512
#define TT   64
#define SLAB (NN*TT)         // 32768 floats per chain slab
#define CSZ  (CH*SLAB)       // floats per full slab
#define NSLAB 4
#define ACCS  3              // slab index for x_st accumulator
#define RTOT  66
#define NB    256            // persistent grid size (co-residency guaranteed)
#define BPAD 68              // padded row stride (floats) for smem tiles
#define BSTRIDE (64*BPAD)    // floats per 64x64 padded buffer

__device__ __align__(16) float g_slab[NSLAB * CSZ];   // ~33.5 MB scratch
__device__ float g_part[4][CH][8][6];                 // step-mod-4 dot partials
__device__ float g_theta[BB][RTOT];
__device__ int   g_arrive[CH];                        // per-chain arrival counters

__device__ __forceinline__ float4 ldcg4(const float* p) {
    return __ldcg((const float4*)p);
}
__device__ __forceinline__ void stcg4(float* p, float4 v) {
    __stcg((float4*)p, v);
}

__device__ __forceinline__ float warp_sum(float v) {
    v += __shfl_down_sync(0xffffffffu, v, 16);
    v += __shfl_down_sync(0xffffffffu, v, 8);
    v += __shfl_down_sync(0xffffffffu, v, 4);
    v += __shfl_down_sync(0xffffffffu, v, 2);
    v += __shfl_down_sync(0xffffffffu, v, 1);
    return v;
}

// Derive d1, d2, 1/norm, theta from the 6 summed dots (L2-coherent reads).
__device__ __forceinline__ void derive_scalars(int buf, int chain, int rUpd,
                                               float* sc) {
    float p0 = 0, p1 = 0, p2 = 0, p3 = 0, p4 = 0, p5 = 0;
    #pragma unroll
    for (int tl = 0; tl < 8; tl++) {
        const float* q = &g_part[buf][chain][tl][0];
        p0 += __ldcg(q + 0); p1 += __ldcg(q + 1); p2 += __ldcg(q + 2);
        p3 += __ldcg(q + 3); p4 += __ldcg(q + 4); p5 += __ldcg(q + 5);
    }
    float d1 = p0;
    float d2 = p1 - d1 * p3;
    float n2 = p2 - 2.f * d1 * p0 - 2.f * d2 * p1
             + d1 * d1 * p4 + d2 * d2 * p5 + 2.f * d1 * d2 * p3;
    sc[0] = d1;
    sc[1] = d2;
    sc[2] = 1.f / fmaxf(sqrtf(fmaxf(n2, 0.f)), 1e-8f);
    sc[3] = g_theta[chain >> 4][rUpd];
}

__device__ __forceinline__ void wait_chain(int chain, int step) {
    int target = 8 * step;
    while (*(volatile int*)&g_arrive[chain] < target) __nanosleep(32);
    __threadfence();
}

// ---------------------------------------------------------------------------
// theta MLP + arrival-counter reset (device globals persist across replays)
// ---------------------------------------------------------------------------
__global__ void k_theta(const float* __restrict__ STE, const float* __restrict__ w1,
                        const float* __restrict__ b1, const float* __restrict__ w2,
                        const float* __restrict__ b2) {
    int idx = threadIdx.x;
    if (idx < CH) g_arrive[idx] = 0;
    if (idx >= BB * RTOT) return;
    int b = idx / RTOT, rr = idx % RTOT;
    int q = rr / 11, p = rr % 11;
    float acc = b2[p];
    #pragma unroll
    for (int s = 0; s < 10; s++) {
        float h1 = b1[q];
        #pragma unroll
        for (int t = 0; t < 5; t++)
            h1 += w1[q * 5 + t] * STE[b * 50 + t * 10 + s];
        acc += w2[p * 10 + s] * h1;
    }
    g_theta[b][rr] = fmaxf(acc, 0.f);
}

// ---------------------------------------------------------------------------
// init: m00 = x / max(||x||_F, eps) into slab 0; acc = theta_0 * m00
// ---------------------------------------------------------------------------
__global__ void __launch_bounds__(256) k_init(const float* __restrict__ x) {
    int chain = blockIdx.x;
    const float* xp = x + chain * SLAB;
    float* m = g_slab + 0 * CSZ + chain * SLAB;
    float* a = g_slab + ACCS * CSZ + chain * SLAB;
    int tid = threadIdx.x;

    float s = 0.f;
    #pragma unroll
    for (int i = 0; i < 32; i++) {
        float4 v = *(const float4*)(xp + (i * 256 + tid) * 4);
        s += v.x * v.x + v.y * v.y + v.z * v.z + v.w * v.w;
    }
    __shared__ float red[8];
    __shared__ float sinv;
    float w = warp_sum(s);
    if ((tid & 31) == 0) red[tid >> 5] = w;
    __syncthreads();
    if (tid == 0) {
        float t = 0.f;
        #pragma unroll
        for (int k = 0; k < 8; k++) t += red[k];
        sinv = 1.f / fmaxf(sqrtf(t), 1e-8f);
    }
    __syncthreads();
    float inv = sinv;
    float th = g_theta[chain >> 4][0];
    #pragma unroll
    for (int i = 0; i < 32; i++) {
        int o = (i * 256 + tid) * 4;
        float4 v = *(const float4*)(xp + o);
        float4 mm, aa;
        mm.x = v.x * inv; mm.y = v.y * inv; mm.z = v.z * inv; mm.w = v.w * inv;
        aa.x = th * mm.x; aa.y = th * mm.y; aa.z = th * mm.z; aa.w = th * mm.w;
        *(float4*)(m + o) = mm;
        *(float4*)(a + o) = aa;
    }
}

// ---------------------------------------------------------------------------
// persistent kernel: all 65 steps, smem/reg-resident temporal state.
// Block bid owns tiles {bid, bid+256}; tile tt = (chain = tt>>3, rt = tt&7).
// dyn smem: B[slot*2+par] (4 x 64x68) then s0, s1 (2 x 64x68).
// ---------------------------------------------------------------------------
__global__ void __launch_bounds__(256, 2) k_persist(
    const float* __restrict__ Ls, const float* __restrict__ Lt)
{
    extern __shared__ float dyn[];
    float* Bb = dyn;                                   // 4 buffers
    float (*s0)[BPAD] = (float(*)[BPAD])(dyn + 4 * BSTRIDE);
    float (*s1)[BPAD] = (float(*)[BPAD])(dyn + 5 * BSTRIDE);
    __shared__ float scal[4];
    __shared__ float red[8][6];
    const int tid = threadIdx.x, bid = blockIdx.x;
    const int tx = tid & 15, ty = tid >> 4;

    int chainA[2], baseA[2], rtA[2];
    #pragma unroll
    for (int slot = 0; slot < 2; slot++) {
        int tt = bid + slot * NB;
        chainA[slot] = tt >> 3;
        rtA[slot] = tt & 7;
        baseA[slot] = (tt >> 3) * SLAB + (tt & 7) * 64 * TT;
    }
    float4 vreg[2][4];        // raw V per slot: [ii] = row ty+16ii, cols tx*4..

    int r = 1;
    for (int i = 0; i <= 10; i++) {
        if (i > 0) {
            // ================= SPATIAL PHASE (step r) =================
            int inS = (i - 1) % 3;
            int secS = (i >= 2) ? (i + 1) % 3 : -1;    // (i-2)%3
            #pragma unroll
            for (int slot = 0; slot < 2; slot++) {
                int chain = chainA[slot], base = baseA[slot], rt = rtA[slot];
                // prologue: normalize pending temporal V (step r-1) -> A only
                if (tid == 0) {
                    wait_chain(chain, r - 1);
                    derive_scalars((r - 1) & 3, chain, r - 1, scal);
                }
                __syncthreads();
                {
                    float d1 = scal[0], d2 = scal[1], inv = scal[2], th = scal[3];
                    float* A = g_slab + ACCS * CSZ + base;
                    const float* L4 = Bb + (slot * 2 + 0) * BSTRIDE;   // m4
                    const float* S3 = Bb + (slot * 2 + 1) * BSTRIDE;   // m3
                    #pragma unroll
                    for (int ii = 0; ii < 4; ii++) {
                        int n = ty + 16 * ii;
                        int o = n * TT + (tx << 2), so = n * BPAD + (tx << 2);
                        float4 l = *(const float4*)(L4 + so);
                        float4 s4 = *(const float4*)(S3 + so);
                        float4 v = vreg[slot][ii];
                        float4 m;
                        m.x = (v.x - d1 * l.x - d2 * s4.x) * inv;
                        m.y = (v.y - d1 * l.y - d2 * s4.y) * inv;
                        m.z = (v.z - d1 * l.z - d2 * s4.z) * inv;
                        m.w = (v.w - d1 * l.w - d2 * s4.w) * inv;
                        float4 a = *(float4*)(A + o);
                        a.x += th * m.x; a.y += th * m.y;
                        a.z += th * m.z; a.w += th * m.w;
                        *(float4*)(A + o) = a;
                    }
                }
                // spatial GEMM: V[n][t] = sum_m Ls[n][m] * X[m][t]
                const float* Xc = g_slab + inS * CSZ + chain * SLAB;
                #pragma unroll
                for (int ii = 0; ii < 4; ii++)
                    vreg[slot][ii] = make_float4(0.f, 0.f, 0.f, 0.f);
                for (int kc = 0; kc < 8; kc++) {
                    __syncthreads();
                    #pragma unroll
                    for (int it = 0; it < 4; it++) {
                        int li = it * 256 + tid;
                        int rr = li >> 4, c4 = (li & 15) << 2;
                        *(float4*)&s0[rr][c4] =
                            *(const float4*)(Ls + (rt * 64 + rr) * NN + kc * 64 + c4);
                        *(float4*)&s1[rr][c4] = ldcg4(Xc + (kc * 64 + rr) * TT + c4);
                    }
                    __syncthreads();
                    #pragma unroll 8
                    for (int k = 0; k < 64; k++) {
                        float b4[4];
                        *(float4*)b4 = *(float4*)&s1[k][tx << 2];
                        #pragma unroll
                        for (int ii = 0; ii < 4; ii++) {
                            float a = s0[ty + 16 * ii][k];
                            vreg[slot][ii].x += a * b4[0];
                            vreg[slot][ii].y += a * b4[1];
                            vreg[slot][ii].z += a * b4[2];
                            vreg[slot][ii].w += a * b4[3];
                        }
                    }
                }
                // dots: L = slab[inS] rows (gmem), S = slab[secS] or 0
                const float* Lr = g_slab + inS * CSZ + base;
                const float* S2 = (secS >= 0) ? (g_slab + secS * CSZ + base) : nullptr;
                float q1 = 0, q2 = 0, q3 = 0, q4 = 0, q5 = 0, q6 = 0;
                #pragma unroll
                for (int ii = 0; ii < 4; ii++) {
                    int n = ty + 16 * ii;
                    float4 lv = ldcg4(Lr + n * TT + (tx << 2));
                    float4 sv = S2 ? ldcg4(S2 + n * TT + (tx << 2))
                                   : make_float4(0.f, 0.f, 0.f, 0.f);
                    float4 vv = vreg[slot][ii];
                    q1 += vv.x * lv.x + vv.y * lv.y + vv.z * lv.z + vv.w * lv.w;
                    q2 += vv.x * sv.x + vv.y * sv.y + vv.z * sv.z + vv.w * sv.w;
                    q3 += vv.x * vv.x + vv.y * vv.y + vv.z * vv.z + vv.w * vv.w;
                    q4 += lv.x * sv.x + lv.y * sv.y + lv.z * sv.z + lv.w * sv.w;
                    q5 += lv.x * lv.x + lv.y * lv.y + lv.z * lv.z + lv.w * lv.w;
                    q6 += sv.x * sv.x + sv.y * sv.y + sv.z * sv.z + sv.w * sv.w;
                }
                float r6[6] = {q1, q2, q3, q4, q5, q6};
                #pragma unroll
                for (int s = 0; s < 6; s++) {
                    float w = warp_sum(r6[s]);
                    if ((tid & 31) == 0) red[tid >> 5][s] = w;
                }
                __syncthreads();
                if (tid == 0) {
                    #pragma unroll
                    for (int s = 0; s < 6; s++) {
                        float t = 0.f;
                        #pragma unroll
                        for (int w = 0; w < 8; w++) t += red[w][s];
                        __stcg(&g_part[r & 3][chain][rt][s], t);
                    }
                    __threadfence();
                    atomicAdd(&g_arrive[chain], 1);
                }
                __syncthreads();
            }
            r++;
        }
        // ================= TEMPORAL PHASES j = 1..5 =================
        for (int j = 1; j <= 5; j++) {
            // load Lt into s0 (spatial clobbers it)
            #pragma unroll
            for (int it = 0; it < 4; it++) {
                int li = it * 256 + tid;
                int rr = li >> 4, c4 = (li & 15) << 2;
                *(float4*)&s0[rr][c4] = *(const float4*)(Lt + rr * TT + c4);
            }
            int curPar = (j - 1) & 1;
            #pragma unroll
            for (int slot = 0; slot < 2; slot++) {
                int chain = chainA[slot], base = baseA[slot], rt = rtA[slot];
                float* Bcur = Bb + (slot * 2 + curPar) * BSTRIDE;        // m_{j-1}
                float* Both = Bb + (slot * 2 + (curPar ^ 1)) * BSTRIDE;  // m_{j-2}
                if (i == 0 && j == 1) {
                    // no pending: load m00 tile from slab0 into Bcur
                    #pragma unroll
                    for (int it = 0; it < 4; it++) {
                        int idx = it * 256 + tid;
                        int n = idx >> 4, t4 = (idx & 15) << 2;
                        *(float4*)&Bcur[n * BPAD + t4] =
                            ldcg4(g_slab + 0 * CSZ + base + n * TT + t4);
                    }
                } else {
                    if (tid == 0) {
                        wait_chain(chain, r - 1);
                        derive_scalars((r - 1) & 3, chain, r - 1, scal);
                    }
                    __syncthreads();
                    float d1 = scal[0], d2 = scal[1], inv = scal[2], th = scal[3];
                    float* A = g_slab + ACCS * CSZ + base;
                    if (j == 1) {
                        // normalize pending SPATIAL V: L,S from gmem; m -> gmem + Bcur
                        const float* Lg = g_slab + ((i - 1) % 3) * CSZ + base;
                        const float* Sg = (i >= 2) ?
                            (g_slab + ((i + 1) % 3) * CSZ + base) : nullptr;
                        float* Mg = g_slab + (i % 3) * CSZ + base;
                        #pragma unroll
                        for (int ii = 0; ii < 4; ii++) {
                            int n = ty + 16 * ii;
                            int o = n * TT + (tx << 2);
                            float4 l = ldcg4(Lg + o);
                            float4 s4 = Sg ? ldcg4(Sg + o)
                                           : make_float4(0.f, 0.f, 0.f, 0.f);
                            float4 v = vreg[slot][ii];
                            float4 m;
                            m.x = (v.x - d1 * l.x - d2 * s4.x) * inv;
                            m.y = (v.y - d1 * l.y - d2 * s4.y) * inv;
                            m.z = (v.z - d1 * l.z - d2 * s4.z) * inv;
                            m.w = (v.w - d1 * l.w - d2 * s4.w) * inv;
                            stcg4(Mg + o, m);
                            *(float4*)&Bcur[n * BPAD + (tx << 2)] = m;
                            float4 a = *(float4*)(A + o);
                            a.x += th * m.x; a.y += th * m.y;
                            a.z += th * m.z; a.w += th * m.w;
                            *(float4*)(A + o) = a;
                        }
                        __threadfence();   // Mg visible before this tile's arrive
                    } else {
                        // normalize pending TEMPORAL V: L = m_{j-2}, S = m_{j-3}
                        #pragma unroll
                        for (int ii = 0; ii < 4; ii++) {
                            int n = ty + 16 * ii;
                            int so = n * BPAD + (tx << 2);
                            int o = n * TT + (tx << 2);
                            float4 l = *(const float4*)(Both + so);
                            float4 s4 = (j == 2) ? make_float4(0.f, 0.f, 0.f, 0.f)
                                                 : *(const float4*)(Bcur + so);
                            float4 v = vreg[slot][ii];
                            float4 m;
                            m.x = (v.x - d1 * l.x - d2 * s4.x) * inv;
                            m.y = (v.y - d1 * l.y - d2 * s4.y) * inv;
                            m.z = (v.z - d1 * l.z - d2 * s4.z) * inv;
                            m.w = (v.w - d1 * l.w - d2 * s4.w) * inv;
                            *(float4*)&Bcur[so] = m;
                            float4 a = *(float4*)(A + o);
                            a.x += th * m.x; a.y += th * m.y;
                            a.z += th * m.z; a.w += th * m.w;
                            *(float4*)(A + o) = a;
                        }
                    }
                }
                __syncthreads();      // Bcur (+Lt on first slot) visible
                // temporal GEMM: V[n][u] = sum_t m[n][t] * Lt[t][u]
                #pragma unroll
                for (int ii = 0; ii < 4; ii++)
                    vreg[slot][ii] = make_float4(0.f, 0.f, 0.f, 0.f);
                #pragma unroll 8
                for (int k = 0; k < 64; k++) {
                    float b4[4];
                    *(float4*)b4 = *(float4*)&s0[k][tx << 2];
                    #pragma unroll
                    for (int ii = 0; ii < 4; ii++) {
                        float a = Bcur[(ty + 16 * ii) * BPAD + k];
                        vreg[slot][ii].x += a * b4[0];
                        vreg[slot][ii].y += a * b4[1];
                        vreg[slot][ii].z += a * b4[2];
                        vreg[slot][ii].w += a * b4[3];
                    }
                }
                // dots: L = Bcur (m_{j-1}), S = m_{j-2} or 0
                float q1 = 0, q2 = 0, q3 = 0, q4 = 0, q5 = 0, q6 = 0;
                #pragma unroll
                for (int ii = 0; ii < 4; ii++) {
                    int n = ty + 16 * ii;
                    int so = n * BPAD + (tx << 2);
                    float4 lv = *(const float4*)(Bcur + so);
                    float4 sv = (j == 1) ? make_float4(0.f, 0.f, 0.f, 0.f)
                                         : *(const float4*)(Both + so);
                    float4 vv = vreg[slot][ii];
                    q1 += vv.x * lv.x + vv.y * lv.y + vv.z * lv.z + vv.w * lv.w;
                    q2 += vv.x * sv.x + vv.y * sv.y + vv.z * sv.z + vv.w * sv.w;
                    q3 += vv.x * vv.x + vv.y * vv.y + vv.z * vv.z + vv.w * vv.w;
                    q4 += lv.x * sv.x + lv.y * sv.y + lv.z * sv.z + lv.w * sv.w;
                    q5 += lv.x * lv.x + lv.y * lv.y + lv.z * lv.z + lv.w * lv.w;
                    q6 += sv.x * sv.x + sv.y * sv.y + sv.z * sv.z + sv.w * sv.w;
                }
                float r6[6] = {q1, q2, q3, q4, q5, q6};
                #pragma unroll
                for (int s = 0; s < 6; s++) {
                    float w = warp_sum(r6[s]);
                    if ((tid & 31) == 0) red[tid >> 5][s] = w;
                }
                __syncthreads();
                if (tid == 0) {
                    #pragma unroll
                    for (int s = 0; s < 6; s++) {
                        float t = 0.f;
                        #pragma unroll
                        for (int w = 0; w < 8; w++) t += red[w][s];
                        __stcg(&g_part[r & 3][chain][rt][s], t);
                    }
                    __threadfence();
                    atomicAdd(&g_arrive[chain], 1);
                }
                __syncthreads();
            }
            r++;
        }
    }
    // ---------------- final pending normalize (step 65): A += theta*m -------
    #pragma unroll
    for (int slot = 0; slot < 2; slot++) {
        int chain = chainA[slot], base = baseA[slot];
        if (tid == 0) {
            wait_chain(chain, r - 1);
            derive_scalars((r - 1) & 3, chain, r - 1, scal);
        }
        __syncthreads();
        float d1 = scal[0], d2 = scal[1], inv = scal[2], th = scal[3];
        float* A = g_slab + ACCS * CSZ + base;
        const float* L4 = Bb + (slot * 2 + 0) * BSTRIDE;   // m4
        const float* S3 = Bb + (slot * 2 + 1) * BSTRIDE;   // m3
        #pragma unroll
        for (int ii = 0; ii < 4; ii++) {
            int n = ty + 16 * ii;
            int o = n * TT + (tx << 2), so = n * BPAD + (tx << 2);
            float4 l = *(const float4*)(L4 + so);
            float4 s4 = *(const float4*)(S3 + so);
            float4 v = vreg[slot][ii];
            float4 a = *(float4*)(A + o);
            a.x += th * (v.x - d1 * l.x - d2 * s4.x) * inv;
            a.y += th * (v.y - d1 * l.y - d2 * s4.y) * inv;
            a.z += th * (v.z - d1 * l.z - d2 * s4.z) * inv;
            a.w += th * (v.w - d1 * l.w - d2 * s4.w) * inv;
            *(float4*)(A + o) = a;
        }
        __syncthreads();
    }
}

// ---------------------------------------------------------------------------
// final: out[b,o,n,t] = BN(W_mlp @ cat(x, x_st) + b)  (BN folded; R9 version)
// ---------------------------------------------------------------------------
__global__ void __launch_bounds__(256) k_final(const float* __restrict__ x,
                                               const float* __restrict__ wm,
                                               const float* __restrict__ bm,
                                               const float* __restrict__ gam,
                                               const float* __restrict__ bet,
                                               const float* __restrict__ mea,
                                               const float* __restrict__ var,
                                               float* __restrict__ out) {
    int b = blockIdx.x;
    int ng = blockIdx.y;                 // group of 4 n values
    __shared__ float sV[4][32][65];
    __shared__ float sW[64][32];
    __shared__ float sb2[64];
    int tid = threadIdx.x;

    for (int i = tid; i < 2048; i += 256) {
        int o = i >> 5, c = i & 31;
        float inv = gam[o] * rsqrtf(var[o] + 1e-5f);
        sW[o][c] = wm[o * 32 + c] * inv;
    }
    if (tid < 64) {
        float inv = gam[tid] * rsqrtf(var[tid] + 1e-5f);
        sb2[tid] = bm[tid] * inv + bet[tid] - mea[tid] * inv;
    }
    for (int i = tid; i < 8192; i += 256) {
        int t = i & 63, c = (i >> 6) & 31, nn = i >> 11;
        int n = ng * 4 + nn;
        float val;
        if (c < 16) val = x[((b * CC + c) * NN + n) * TT + t];
        else        val = g_slab[ACCS * CSZ + (b * CC + (c - 16)) * SLAB + n * TT + t];
        sV[nn][c][t] = val;
    }
    __syncthreads();

    int tg = tid & 63, og = tid >> 6;
    #pragma unroll 1
    for (int oo = 0; oo < 16; oo++) {
        int o = og * 16 + oo;
        float bb = sb2[o];
        float a0 = bb, a1 = bb, a2 = bb, a3 = bb;
        #pragma unroll
        for (int c = 0; c < 32; c++) {
            float w = sW[o][c];
            a0 += w * sV[0][c][tg];
            a1 += w * sV[1][c][tg];
            a2 += w * sV[2][c][tg];
            a3 += w * sV[3][c][tg];
        }
        int n0 = ng * 4;
        float* op = out + ((b * 64 + o) * NN + n0) * TT + tg;
        op[0 * TT] = a0;
        op[1 * TT] = a1;
        op[2 * TT] = a2;
        op[3 * TT] = a3;
    }
}

// ---------------------------------------------------------------------------
// host: 4-node launch sequence (graph-capturable: launches only)
// ---------------------------------------------------------------------------
extern "C" void kernel_launch(void* const* d_in, const int* in_sizes, int n_in,
                              void* d_out, int out_size) {
    const float* x   = (const float*)d_in[0];
    const float* Ls  = (const float*)d_in[1];
    const float* Lt  = (const float*)d_in[2];
    const float* STE = (const float*)d_in[3];
    const float* w1  = (const float*)d_in[4];
    const float* b1  = (const float*)d_in[5];
    const float* w2  = (const float*)d_in[6];
    const float* b2  = (const float*)d_in[7];
    const float* wm  = (const float*)d_in[8];
    const float* bm  = (const float*)d_in[9];
    const float* gam = (const float*)d_in[10];
    const float* bet = (const float*)d_in[11];
    const float* mea = (const float*)d_in[12];
    const float* var = (const float*)d_in[13];
    float* out = (float*)d_out;
    (void)in_sizes; (void)n_in; (void)out_size;

    const int dynBytes = 6 * BSTRIDE * (int)sizeof(float);   // 104448
    cudaFuncSetAttribute(k_persist,
                         cudaFuncAttributeMaxDynamicSharedMemorySize, dynBytes);

    k_theta<<<1, 288>>>(STE, w1, b1, w2, b2);
    k_init<<<64, 256>>>(x);
    k_persist<<<NB, 256, dynBytes>>>(Ls, Lt);
    k_final<<<dim3(4, 128), 256>>>(x, wm, bm, gam, bet, mea, var, out);
}